// round 14
// baseline (speedup 1.0000x reference)
#include <cuda_runtime.h>
#include <math.h>

#define BGRAPH 256
#define NPG0   400
#define DEG    16
#define HDIM   128
#define NLAY   5
#define NNODE  (BGRAPH*NPG0)      /* 102400 */
#define NEDGE  (NNODE*DEG)        /* 1638400 */
#define NPG1   320
#define NPG2   256
#define NAL1   (BGRAPH*NPG1)      /* 81920 */
#define NAL2   (BGRAPH*NPG2)      /* 65536 */
#define NSM    148
#define CAP    64                 /* bucket capacity per node (P(deg>64) ~ 0) */

// ---------------- device scratch (static, allowed) ----------------
__device__ float d_XA[(size_t)NNODE*HDIM];
__device__ float d_XB[(size_t)NNODE*HDIM];
__device__ float d_MEAN[(size_t)NNODE*HDIM];
__device__ int   d_fill[NNODE];
__device__ int   d_cols[(size_t)NNODE*CAP];
__device__ float d_p[NNODE];
__device__ float d_q[NNODE];
__device__ float d_score[NNODE];
__device__ float d_tsc[NAL1];
__device__ float d_xs[NLAY*BGRAPH*HDIM];
__device__ int   d_perm1[NAL1];    // space1 -> orig
__device__ int   d_perm2s[NAL2];   // space2 -> space1
__device__ int   d_permO2[NAL2];   // space2 -> orig
__device__ int   d_map1[NNODE];    // orig -> space1 | -1
__device__ int   d_map2[NNODE];    // orig -> space2 | -1

__device__ __forceinline__ const float* selX(const float* xext, int sel) {
    return sel == 0 ? xext : (sel == 1 ? d_XA : d_XB);
}
__device__ __forceinline__ float* selXw(int sel) {
    return sel == 1 ? d_XA : d_XB;
}

// packed fp32x2 (sm_103a FFMA2, exact fp32 semantics)
__device__ __forceinline__ void fma2(unsigned long long& d,
                                     unsigned long long a,
                                     unsigned long long b) {
    asm("fma.rn.f32x2 %0, %1, %2, %0;" : "+l"(d) : "l"(a), "l"(b));
}
__device__ __forceinline__ float2 unpack2(unsigned long long v) {
    float2 r;
    asm("mov.b64 {%0, %1}, %2;" : "=f"(r.x), "=f"(r.y) : "l"(v));
    return r;
}

// ---------------- bucket build ----------------
__global__ void init_k() {
    int v = blockIdx.x * blockDim.x + threadIdx.x;
    if (v < NNODE) { d_fill[v] = 0; d_map1[v] = -1; d_map2[v] = -1; }
}

__global__ void scatter_k(const int* __restrict__ ei) {
    int e = blockIdx.x * blockDim.x + threadIdx.x;
    if (e < NEDGE) {
        int dst = ei[NEDGE + e];
        int pos = atomicAdd(&d_fill[dst], 1);
        d_cols[(size_t)dst * CAP + pos] = ei[e];
    }
}

// ---------------- mean aggregation, graph-per-CTA (L1-resident) --------------
__global__ void __launch_bounds__(1024, 1) agg_full_g(const float* __restrict__ xext,
                                                      int xsel) {
    const float* X = selX(xext, xsel);
    int w = threadIdx.x >> 5, lane = threadIdx.x & 31;
    for (int b = blockIdx.x; b < BGRAPH; b += gridDim.x) {
        for (int r = w; r < NPG0; r += 32) {
            int v = b * NPG0 + r;
            const int* col = &d_cols[(size_t)v * CAP];
            int cnt = d_fill[v];
            float4 acc = make_float4(0.f, 0.f, 0.f, 0.f);
            for (int e = 0; e < cnt; e++) {
                int u = col[e];
                float4 xv = ((const float4*)(X + (size_t)u * HDIM))[lane];
                acc.x += xv.x; acc.y += xv.y; acc.z += xv.z; acc.w += xv.w;
            }
            float inv = 1.0f / (float)(cnt < 1 ? 1 : cnt);
            acc.x *= inv; acc.y *= inv; acc.z *= inv; acc.w *= inv;
            ((float4*)(d_MEAN + (size_t)v * HDIM))[lane] = acc;
        }
    }
}

__global__ void __launch_bounds__(1024, 1) agg_c_g(int xsel, int npg,
                                                   const int* __restrict__ perm,
                                                   const int* __restrict__ map) {
    const float* X = selX(nullptr, xsel);
    int w = threadIdx.x >> 5, lane = threadIdx.x & 31;
    for (int b = blockIdx.x; b < BGRAPH; b += gridDim.x) {
        for (int r = w; r < npg; r += 32) {
            int i = b * npg + r;
            int v = perm[i];
            const int* col = &d_cols[(size_t)v * CAP];
            int cnt = d_fill[v];
            float4 acc = make_float4(0.f, 0.f, 0.f, 0.f);
            int c = 0;
            for (int e = 0; e < cnt; e++) {
                int m = map[col[e]];
                if (m >= 0) {
                    c++;
                    float4 xv = ((const float4*)(X + (size_t)m * HDIM))[lane];
                    acc.x += xv.x; acc.y += xv.y; acc.z += xv.z; acc.w += xv.w;
                }
            }
            float inv = 1.0f / (float)(c < 1 ? 1 : c);
            acc.x *= inv; acc.y *= inv; acc.z *= inv; acc.w *= inv;
            ((float4*)(d_MEAN + (size_t)i * HDIM))[lane] = acc;
        }
    }
}

// ---------------- fused conv GEMM: OUT = relu(MEAN@Wr + X@Ws + b) ------------
// FFMA2, single-buffered, VECTORIZED staging (float4 LDG, STS.128/st.v2).
#define AS2_STRIDE 260
__global__ void __launch_bounds__(256, 2) gemm_k(const float* __restrict__ xext,
                                                 int xsel, int osel,
                                                 const float* __restrict__ Wr,
                                                 const float* __restrict__ Ws,
                                                 const float* __restrict__ bias) {
    __shared__ __align__(16) float As2[16][AS2_STRIDE];
    __shared__ __align__(16) float Bs[16][128];
    int row0 = blockIdx.x * 128;
    int tid = threadIdx.x;
    int tx = tid & 15, ty = tid >> 4;

    // vectorized staging mapping
    int lm  = tid >> 1;          // A row 0..127
    int lc  = (tid & 1) * 8;     // A k-group {0,8}
    int lkB = tid >> 4;          // B row 0..15
    int lnB = (tid & 15) * 8;    // B col group

    unsigned long long acc[8][4];
#pragma unroll
    for (int i = 0; i < 8; i++)
#pragma unroll
        for (int j = 0; j < 4; j++) acc[i][j] = 0ull;

    const float* Xin = selX(xext, xsel);
    for (int phase = 0; phase < 2; ++phase) {
        const float* A = phase ? Xin : d_MEAN;
        const float* W = phase ? Ws : Wr;
        for (int k0 = 0; k0 < 128; k0 += 16) {
            // A: 2x LDG.128, then 8 duplicated st.v2 (crossbar-optimal)
            {
                const float4* pa = (const float4*)(A + (size_t)(row0 + lm) * HDIM + k0 + lc);
                float4 a0 = pa[0], a1 = pa[1];
                float av[8] = {a0.x, a0.y, a0.z, a0.w, a1.x, a1.y, a1.z, a1.w};
                unsigned sa = (unsigned)__cvta_generic_to_shared(&As2[lc][2 * lm]);
#pragma unroll
                for (int j = 0; j < 8; j++)
                    asm volatile("st.shared.v2.f32 [%0], {%1, %1};"
                                 :: "r"(sa + j * AS2_STRIDE * 4), "f"(av[j]));
            }
            // B: 2x LDG.128 -> 2x STS.128
            {
                const float4* pb = (const float4*)(W + (k0 + lkB) * HDIM + lnB);
                float4 b0 = pb[0], b1 = pb[1];
                *(float4*)&Bs[lkB][lnB]     = b0;
                *(float4*)&Bs[lkB][lnB + 4] = b1;
            }
            __syncthreads();
#pragma unroll
            for (int kk = 0; kk < 16; kk++) {
                const ulonglong2* pa = (const ulonglong2*)&As2[kk][16 * ty];
                ulonglong2 A0 = pa[0], A1 = pa[1], A2 = pa[2], A3 = pa[3];
                const ulonglong2* pb = (const ulonglong2*)&Bs[kk][8 * tx];
                ulonglong2 B0 = pb[0], B1 = pb[1];
                unsigned long long a[8] = {A0.x, A0.y, A1.x, A1.y, A2.x, A2.y, A3.x, A3.y};
                unsigned long long b[4] = {B0.x, B0.y, B1.x, B1.y};
#pragma unroll
                for (int i = 0; i < 8; i++)
#pragma unroll
                    for (int j = 0; j < 4; j++) fma2(acc[i][j], a[i], b[j]);
            }
            __syncthreads();
        }
    }
    float* OUT = selXw(osel);
    float4 bv0 = *(const float4*)&bias[tx * 8];
    float4 bv1 = *(const float4*)&bias[tx * 8 + 4];
#pragma unroll
    for (int i = 0; i < 8; i++) {
        int gr = row0 + ty * 8 + i;
        float2 v0 = unpack2(acc[i][0]);
        float2 v1 = unpack2(acc[i][1]);
        float2 v2 = unpack2(acc[i][2]);
        float2 v3 = unpack2(acc[i][3]);
        float4 o0, o1;
        o0.x = fmaxf(v0.x + bv0.x, 0.f);
        o0.y = fmaxf(v0.y + bv0.y, 0.f);
        o0.z = fmaxf(v1.x + bv0.z, 0.f);
        o0.w = fmaxf(v1.y + bv0.w, 0.f);
        o1.x = fmaxf(v2.x + bv1.x, 0.f);
        o1.y = fmaxf(v2.y + bv1.y, 0.f);
        o1.z = fmaxf(v3.x + bv1.z, 0.f);
        o1.w = fmaxf(v3.y + bv1.w, 0.f);
        float4* orow = (float4*)(OUT + (size_t)gr * HDIM + tx * 8);
        orow[0] = o0;
        orow[1] = o1;
    }
}

// ---------------- per-graph mean pool (contiguous rows, no masks) ------------
__global__ void __launch_bounds__(512) gmean_k(const float* __restrict__ xext,
                                               int xsel, int layer, int npg, float inv) {
    __shared__ float red[4][128];
    int b = blockIdx.x;
    int h = threadIdx.x & 127;
    int g = threadIdx.x >> 7;
    const float* X = selX(xext, xsel);
    int base = b * npg;
    float s = 0.f;
    for (int r = g; r < npg; r += 4)
        s += X[(size_t)(base + r) * HDIM + h];
    red[g][h] = s;
    __syncthreads();
    if (g == 0) {
        float t = red[0][h] + red[1][h] + red[2][h] + red[3][h];
        d_xs[(layer * BGRAPH + b) * HDIM + h] = t * inv;
    }
}

// ---------------- pool scoring ----------------
__global__ void dots_k(const float* __restrict__ xext, int xsel, int n,
                       const float* __restrict__ wr, const float* __restrict__ ws) {
    int g = blockIdx.x * blockDim.x + threadIdx.x;
    int w = g >> 5, lane = g & 31;
    if (w >= n) return;
    const float* X = selX(xext, xsel);
    float4 xv = ((const float4*)(X + (size_t)w * HDIM))[lane];
    float4 a = ((const float4*)wr)[lane];
    float4 b = ((const float4*)ws)[lane];
    float pp = xv.x * a.x + xv.y * a.y + xv.z * a.z + xv.w * a.w;
    float qq = xv.x * b.x + xv.y * b.y + xv.z * b.z + xv.w * b.w;
#pragma unroll
    for (int o = 16; o; o >>= 1) {
        pp += __shfl_down_sync(0xFFFFFFFFu, pp, o);
        qq += __shfl_down_sync(0xFFFFFFFFu, qq, o);
    }
    if (lane == 0) { d_p[w] = pp; d_q[w] = qq; }
}

// pool1 score: original space, everything alive — no masks
__global__ void score1_k(const float* __restrict__ pb) {
    int v = blockIdx.x * blockDim.x + threadIdx.x;
    if (v >= NNODE) return;
    const int* col = &d_cols[(size_t)v * CAP];
    int cnt = d_fill[v];
    float s = 0.f;
    for (int e = 0; e < cnt; e++) s += d_p[col[e]];
    d_score[v] = s / (float)(cnt < 1 ? 1 : cnt) + d_q[v] + pb[0];
}

// pool2 score: compact space1
__global__ void score2_k(const float* __restrict__ pb,
                         const int* __restrict__ perm,
                         const int* __restrict__ map, int n) {
    int i = blockIdx.x * blockDim.x + threadIdx.x;
    if (i >= n) return;
    int v = perm[i];
    const int* col = &d_cols[(size_t)v * CAP];
    int cnt = d_fill[v];
    float s = 0.f; int c = 0;
    for (int e = 0; e < cnt; e++) {
        int m = map[col[e]];
        if (m >= 0) { s += d_p[m]; c++; }
    }
    d_score[i] = s / (float)(c < 1 ? 1 : c) + d_q[i] + pb[0];
}

// ---------------- per-graph top-k (bitonic 512, contiguous all-alive) --------
__global__ void __launch_bounds__(512) topk_k(int npg, int k, int* __restrict__ perm_out) {
    __shared__ float sc[512];
    __shared__ int   id[512];
    int b = blockIdx.x, tid = threadIdx.x;
    if (tid < npg) {
        sc[tid] = d_score[b * npg + tid];
        id[tid] = b * npg + tid;
    } else {
        sc[tid] = -INFINITY;
        id[tid] = 0x7FFFFFFF;
    }
    __syncthreads();
    for (int kk = 2; kk <= 512; kk <<= 1) {
        for (int j = kk >> 1; j > 0; j >>= 1) {
            int i = tid, ixj = i ^ j;
            if (ixj > i) {
                float s1 = sc[i], s2 = sc[ixj];
                int i1 = id[i], i2 = id[ixj];
                bool beforeIxj = (s2 > s1) || (s2 == s1 && i2 < i1);
                bool up = ((i & kk) == 0);
                if (up ? beforeIxj : !beforeIxj) {
                    sc[i] = s2; sc[ixj] = s1;
                    id[i] = i2; id[ixj] = i1;
                }
            }
            __syncthreads();
        }
    }
    if (tid < k) {
        perm_out[b * k + tid] = id[tid];
        d_tsc[b * k + tid] = tanhf(sc[tid]);
    }
}

// compose for pool2: permO2 = perm1[perm2s]; map2[orig] = space2 idx
__global__ void compose_k() {
    int i = blockIdx.x * blockDim.x + threadIdx.x;
    if (i >= NAL2) return;
    int i1 = d_perm2s[i];
    int o = d_perm1[i1];
    d_permO2[i] = o;
    d_map2[o] = i;
}

// compact + tanh-scale: dst[w] = src[perm[w]] * tsc[w]; also fills map1 on pool1
__global__ void compact_k(int srcsel, int dstsel, const int* __restrict__ perm,
                          int n, int* __restrict__ map_or_null) {
    int g = blockIdx.x * blockDim.x + threadIdx.x;
    int w = g >> 5, lane = g & 31;
    if (w >= n) return;
    int src_row = perm[w];
    if (map_or_null && lane == 0) map_or_null[src_row] = w;
    float t = d_tsc[w];
    const float* S = selX(nullptr, srcsel);
    float* D = selXw(dstsel);
    float4 v = ((const float4*)(S + (size_t)src_row * HDIM))[lane];
    v.x *= t; v.y *= t; v.z *= t; v.w *= t;
    ((float4*)(D + (size_t)w * HDIM))[lane] = v;
}

// ---------------- MLP head ----------------
__global__ void head_k(const float* __restrict__ l1w, const float* __restrict__ l1b,
                       const float* __restrict__ l2w, const float* __restrict__ l2b,
                       float* __restrict__ out) {
    int b = blockIdx.x, h = threadIdx.x;
    float acc = l1b[h];
#pragma unroll 2
    for (int l = 0; l < NLAY; l++) {
        const float* xr = &d_xs[(l * BGRAPH + b) * HDIM];
#pragma unroll 8
        for (int kk = 0; kk < HDIM; kk++) {
            acc += xr[kk] * l1w[(l * HDIM + kk) * HDIM + h];
        }
    }
    acc = fmaxf(acc, 0.f);
    __shared__ float s0[128], s1[128];
    s0[h] = acc * l2w[h * 2 + 0];
    s1[h] = acc * l2w[h * 2 + 1];
    __syncthreads();
    for (int off = 64; off; off >>= 1) {
        if (h < off) { s0[h] += s0[h + off]; s1[h] += s1[h + off]; }
        __syncthreads();
    }
    if (h == 0) {
        float l0 = s0[0] + l2b[0];
        float l1 = s1[0] + l2b[1];
        float m = fmaxf(l0, l1);
        float lse = m + logf(expf(l0 - m) + expf(l1 - m));
        out[b * 2 + 0] = l0 - lse;
        out[b * 2 + 1] = l1 - lse;
    }
}

// ---------------- launch ----------------
extern "C" void kernel_launch(void* const* d_in, const int* in_sizes, int n_in,
                              void* d_out, int out_size) {
    const float* x    = (const float*)d_in[0];
    const int*   ei   = (const int*)d_in[1];
    const float* c1wr = (const float*)d_in[3];
    const float* c1ws = (const float*)d_in[4];
    const float* c1b  = (const float*)d_in[5];
    const float* cwr  = (const float*)d_in[6];
    const float* cws  = (const float*)d_in[7];
    const float* cb   = (const float*)d_in[8];
    const float* pwr  = (const float*)d_in[9];
    const float* pws  = (const float*)d_in[10];
    const float* pb   = (const float*)d_in[11];
    const float* l1w  = (const float*)d_in[12];
    const float* l1b  = (const float*)d_in[13];
    const float* l2w  = (const float*)d_in[14];
    const float* l2b  = (const float*)d_in[15];
    float* out = (float*)d_out;

    const int WPB = 256;

    int *perm1, *perm2s, *permO2, *map1, *map2;
    cudaGetSymbolAddress((void**)&perm1, d_perm1);
    cudaGetSymbolAddress((void**)&perm2s, d_perm2s);
    cudaGetSymbolAddress((void**)&permO2, d_permO2);
    cudaGetSymbolAddress((void**)&map1, d_map1);
    cudaGetSymbolAddress((void**)&map2, d_map2);

    // bucket build
    init_k<<<NNODE / WPB, WPB>>>();        // launch 0
    scatter_k<<<NEDGE / WPB, WPB>>>(ei);   // launch 1

    // conv1: x(ext) -> XA ; xs[0]
    agg_full_g<<<NSM, 1024>>>(x, 0);       // launch 2
    gemm_k<<<NNODE / 128, 256>>>(x, 0, 1, c1wr, c1ws, c1b);  // launch 3 (profiled)
    gmean_k<<<BGRAPH, 512>>>(x, 1, 0, NPG0, 1.0f / 400.0f);

    // conv2: XA -> XB ; xs[1]
    agg_full_g<<<NSM, 1024>>>(x, 1);
    gemm_k<<<NNODE / 128, 256>>>(x, 1, 2, cwr + 0 * HDIM * HDIM, cws + 0 * HDIM * HDIM, cb + 0 * HDIM);
    gmean_k<<<BGRAPH, 512>>>(x, 2, 1, NPG0, 1.0f / 400.0f);

    // pool1: original -> space1 (contiguous 320/graph), compact XB -> XA
    dots_k<<<NNODE / 8, WPB>>>(x, 2, NNODE, pwr + 0 * HDIM, pws + 0 * HDIM);
    score1_k<<<NNODE / WPB, WPB>>>(pb + 0);
    topk_k<<<BGRAPH, 512>>>(NPG0, NPG1, perm1);
    compact_k<<<NAL1 / 8, WPB>>>(2, 1, perm1, NAL1, map1);

    // conv3 (space1): XA -> XB ; xs[2]
    agg_c_g<<<NSM, 1024>>>(1, NPG1, perm1, map1);
    gemm_k<<<NAL1 / 128, 256>>>(x, 1, 2, cwr + 1 * HDIM * HDIM, cws + 1 * HDIM * HDIM, cb + 1 * HDIM);
    gmean_k<<<BGRAPH, 512>>>(x, 2, 2, NPG1, 1.0f / 320.0f);

    // conv4 (space1): XB -> XA ; xs[3]
    agg_c_g<<<NSM, 1024>>>(2, NPG1, perm1, map1);
    gemm_k<<<NAL1 / 128, 256>>>(x, 2, 1, cwr + 2 * HDIM * HDIM, cws + 2 * HDIM * HDIM, cb + 2 * HDIM);
    gmean_k<<<BGRAPH, 512>>>(x, 1, 3, NPG1, 1.0f / 320.0f);

    // pool2: space1 -> space2 (contiguous 256/graph), compact XA -> XB
    dots_k<<<NAL1 / 8, WPB>>>(x, 1, NAL1, pwr + 1 * HDIM, pws + 1 * HDIM);
    score2_k<<<NAL1 / WPB, WPB>>>(pb + 1, perm1, map1, NAL1);
    topk_k<<<BGRAPH, 512>>>(NPG1, NPG2, perm2s);
    compose_k<<<NAL2 / WPB, WPB>>>();
    compact_k<<<NAL2 / 8, WPB>>>(1, 2, perm2s, NAL2, nullptr);

    // conv5 (space2): XB -> XA ; xs[4]
    agg_c_g<<<NSM, 1024>>>(2, NPG2, permO2, map2);
    gemm_k<<<NAL2 / 128, 256>>>(x, 2, 1, cwr + 3 * HDIM * HDIM, cws + 3 * HDIM * HDIM, cb + 3 * HDIM);
    gmean_k<<<BGRAPH, 512>>>(x, 1, 4, NPG2, 1.0f / 256.0f);

    // head
    head_k<<<BGRAPH, HDIM>>>(l1w, l1b, l2w, l2b, out);
}

// round 15
// speedup vs baseline: 1.0419x; 1.0419x over previous
#include <cuda_runtime.h>
#include <math.h>

#define BGRAPH 256
#define NPG0   400
#define DEG    16
#define HDIM   128
#define NLAY   5
#define NNODE  (BGRAPH*NPG0)      /* 102400 */
#define NEDGE  (NNODE*DEG)        /* 1638400 */
#define NPG1   320
#define NPG2   256
#define NAL1   (BGRAPH*NPG1)      /* 81920 */
#define NAL2   (BGRAPH*NPG2)      /* 65536 */
#define NSM    148
#define CAP    64                 /* bucket capacity per node (P(deg>64) ~ 0) */

// ---------------- device scratch (static, allowed) ----------------
__device__ float d_XA[(size_t)NNODE*HDIM];
__device__ float d_XB[(size_t)NNODE*HDIM];
__device__ float d_MEAN[(size_t)NNODE*HDIM];
__device__ int   d_fill[NNODE];
__device__ int   d_cols[(size_t)NNODE*CAP];
__device__ float d_p[NNODE];
__device__ float d_q[NNODE];
__device__ float d_score[NNODE];
__device__ float d_tsc[NAL1];
__device__ float d_xs[NLAY*BGRAPH*HDIM];
__device__ int   d_perm1[NAL1];
__device__ int   d_perm2s[NAL2];
__device__ int   d_permO2[NAL2];
__device__ int   d_map1[NNODE];
__device__ int   d_map2[NNODE];

__device__ __forceinline__ const float* selX(const float* xext, int sel) {
    return sel == 0 ? xext : (sel == 1 ? d_XA : d_XB);
}
__device__ __forceinline__ float* selXw(int sel) {
    return sel == 1 ? d_XA : d_XB;
}

// packed fp32x2 (sm_103a FFMA2, exact fp32 semantics)
__device__ __forceinline__ void fma2(unsigned long long& d,
                                     unsigned long long a,
                                     unsigned long long b) {
    asm("fma.rn.f32x2 %0, %1, %2, %0;" : "+l"(d) : "l"(a), "l"(b));
}
__device__ __forceinline__ float2 unpack2(unsigned long long v) {
    float2 r;
    asm("mov.b64 {%0, %1}, %2;" : "=f"(r.x), "=f"(r.y) : "l"(v));
    return r;
}

// ---------------- bucket build ----------------
__global__ void init_k() {
    int v = blockIdx.x * blockDim.x + threadIdx.x;
    if (v < NNODE) { d_fill[v] = 0; d_map1[v] = -1; d_map2[v] = -1; }
}

__global__ void scatter_k(const int* __restrict__ ei) {
    int e = blockIdx.x * blockDim.x + threadIdx.x;
    if (e < NEDGE) {
        int dst = ei[NEDGE + e];
        int pos = atomicAdd(&d_fill[dst], 1);
        d_cols[(size_t)dst * CAP + pos] = ei[e];
    }
}

// ---------------- mean aggregation, graph-per-CTA (L1-resident) --------------
__global__ void __launch_bounds__(1024, 1) agg_full_g(const float* __restrict__ xext,
                                                      int xsel) {
    const float* X = selX(xext, xsel);
    int w = threadIdx.x >> 5, lane = threadIdx.x & 31;
    for (int b = blockIdx.x; b < BGRAPH; b += gridDim.x) {
        for (int r = w; r < NPG0; r += 32) {
            int v = b * NPG0 + r;
            const int* col = &d_cols[(size_t)v * CAP];
            int cnt = d_fill[v];
            float4 acc = make_float4(0.f, 0.f, 0.f, 0.f);
            for (int e = 0; e < cnt; e++) {
                int u = col[e];
                float4 xv = ((const float4*)(X + (size_t)u * HDIM))[lane];
                acc.x += xv.x; acc.y += xv.y; acc.z += xv.z; acc.w += xv.w;
            }
            float inv = 1.0f / (float)(cnt < 1 ? 1 : cnt);
            acc.x *= inv; acc.y *= inv; acc.z *= inv; acc.w *= inv;
            ((float4*)(d_MEAN + (size_t)v * HDIM))[lane] = acc;
        }
    }
}

__global__ void __launch_bounds__(1024, 1) agg_c_g(int xsel, int npg,
                                                   const int* __restrict__ perm,
                                                   const int* __restrict__ map) {
    const float* X = selX(nullptr, xsel);
    int w = threadIdx.x >> 5, lane = threadIdx.x & 31;
    for (int b = blockIdx.x; b < BGRAPH; b += gridDim.x) {
        for (int r = w; r < npg; r += 32) {
            int i = b * npg + r;
            int v = perm[i];
            const int* col = &d_cols[(size_t)v * CAP];
            int cnt = d_fill[v];
            float4 acc = make_float4(0.f, 0.f, 0.f, 0.f);
            int c = 0;
            for (int e = 0; e < cnt; e++) {
                int m = map[col[e]];
                if (m >= 0) {
                    c++;
                    float4 xv = ((const float4*)(X + (size_t)m * HDIM))[lane];
                    acc.x += xv.x; acc.y += xv.y; acc.z += xv.z; acc.w += xv.w;
                }
            }
            float inv = 1.0f / (float)(c < 1 ? 1 : c);
            acc.x *= inv; acc.y *= inv; acc.z *= inv; acc.w *= inv;
            ((float4*)(d_MEAN + (size_t)i * HDIM))[lane] = acc;
        }
    }
}

// ---------------- fused conv GEMM (R12 proven scalar-staged version) ----------
#define AS2_STRIDE 260
__global__ void __launch_bounds__(256, 2) gemm_k(const float* __restrict__ xext,
                                                 int xsel, int osel,
                                                 const float* __restrict__ Wr,
                                                 const float* __restrict__ Ws,
                                                 const float* __restrict__ bias) {
    __shared__ __align__(16) float As2[16][AS2_STRIDE];
    __shared__ __align__(16) float Bs[16][128];
    int row0 = blockIdx.x * 128;
    int tid = threadIdx.x;
    int tx = tid & 15, ty = tid >> 4;

    unsigned long long acc[8][4];
#pragma unroll
    for (int i = 0; i < 8; i++)
#pragma unroll
        for (int j = 0; j < 4; j++) acc[i][j] = 0ull;

    const float* Xin = selX(xext, xsel);
    for (int phase = 0; phase < 2; ++phase) {
        const float* A = phase ? Xin : d_MEAN;
        const float* W = phase ? Ws : Wr;
        for (int k0 = 0; k0 < 128; k0 += 16) {
#pragma unroll
            for (int r = 0; r < 8; r++) {
                int idx = tid + r * 256;
                int m = idx >> 4, kk = idx & 15;
                float v = A[(size_t)(row0 + m) * HDIM + k0 + kk];
                unsigned saddr = (unsigned)__cvta_generic_to_shared(&As2[kk][2 * m]);
                asm volatile("st.shared.v2.f32 [%0], {%1, %1};" :: "r"(saddr), "f"(v));
            }
#pragma unroll
            for (int r = 0; r < 8; r++) {
                int idx = tid + r * 256;
                int kk = idx >> 7, n = idx & 127;
                Bs[kk][n] = W[(k0 + kk) * HDIM + n];
            }
            __syncthreads();
#pragma unroll
            for (int kk = 0; kk < 16; kk++) {
                const ulonglong2* pa = (const ulonglong2*)&As2[kk][16 * ty];
                ulonglong2 A0 = pa[0], A1 = pa[1], A2 = pa[2], A3 = pa[3];
                const ulonglong2* pb = (const ulonglong2*)&Bs[kk][8 * tx];
                ulonglong2 B0 = pb[0], B1 = pb[1];
                unsigned long long a[8] = {A0.x, A0.y, A1.x, A1.y, A2.x, A2.y, A3.x, A3.y};
                unsigned long long b[4] = {B0.x, B0.y, B1.x, B1.y};
#pragma unroll
                for (int i = 0; i < 8; i++)
#pragma unroll
                    for (int j = 0; j < 4; j++) fma2(acc[i][j], a[i], b[j]);
            }
            __syncthreads();
        }
    }
    float* OUT = selXw(osel);
    float4 bv0 = *(const float4*)&bias[tx * 8];
    float4 bv1 = *(const float4*)&bias[tx * 8 + 4];
#pragma unroll
    for (int i = 0; i < 8; i++) {
        int gr = row0 + ty * 8 + i;
        float2 v0 = unpack2(acc[i][0]);
        float2 v1 = unpack2(acc[i][1]);
        float2 v2 = unpack2(acc[i][2]);
        float2 v3 = unpack2(acc[i][3]);
        float4 o0, o1;
        o0.x = fmaxf(v0.x + bv0.x, 0.f);
        o0.y = fmaxf(v0.y + bv0.y, 0.f);
        o0.z = fmaxf(v1.x + bv0.z, 0.f);
        o0.w = fmaxf(v1.y + bv0.w, 0.f);
        o1.x = fmaxf(v2.x + bv1.x, 0.f);
        o1.y = fmaxf(v2.y + bv1.y, 0.f);
        o1.z = fmaxf(v3.x + bv1.z, 0.f);
        o1.w = fmaxf(v3.y + bv1.w, 0.f);
        float4* orow = (float4*)(OUT + (size_t)gr * HDIM + tx * 8);
        orow[0] = o0;
        orow[1] = o1;
    }
}

// ---------------- per-graph mean pool (contiguous rows, no masks) ------------
__global__ void __launch_bounds__(512) gmean_k(const float* __restrict__ xext,
                                               int xsel, int layer, int npg, float inv) {
    __shared__ float red[4][128];
    int b = blockIdx.x;
    int h = threadIdx.x & 127;
    int g = threadIdx.x >> 7;
    const float* X = selX(xext, xsel);
    int base = b * npg;
    float s = 0.f;
    for (int r = g; r < npg; r += 4)
        s += X[(size_t)(base + r) * HDIM + h];
    red[g][h] = s;
    __syncthreads();
    if (g == 0) {
        float t = red[0][h] + red[1][h] + red[2][h] + red[3][h];
        d_xs[(layer * BGRAPH + b) * HDIM + h] = t * inv;
    }
}

// ---------------- pool scoring ----------------
__global__ void dots_k(const float* __restrict__ xext, int xsel, int n,
                       const float* __restrict__ wr, const float* __restrict__ ws) {
    int g = blockIdx.x * blockDim.x + threadIdx.x;
    int w = g >> 5, lane = g & 31;
    if (w >= n) return;
    const float* X = selX(xext, xsel);
    float4 xv = ((const float4*)(X + (size_t)w * HDIM))[lane];
    float4 a = ((const float4*)wr)[lane];
    float4 b = ((const float4*)ws)[lane];
    float pp = xv.x * a.x + xv.y * a.y + xv.z * a.z + xv.w * a.w;
    float qq = xv.x * b.x + xv.y * b.y + xv.z * b.z + xv.w * b.w;
#pragma unroll
    for (int o = 16; o; o >>= 1) {
        pp += __shfl_down_sync(0xFFFFFFFFu, pp, o);
        qq += __shfl_down_sync(0xFFFFFFFFu, qq, o);
    }
    if (lane == 0) { d_p[w] = pp; d_q[w] = qq; }
}

__global__ void score1_k(const float* __restrict__ pb) {
    int v = blockIdx.x * blockDim.x + threadIdx.x;
    if (v >= NNODE) return;
    const int* col = &d_cols[(size_t)v * CAP];
    int cnt = d_fill[v];
    float s = 0.f;
    for (int e = 0; e < cnt; e++) s += d_p[col[e]];
    d_score[v] = s / (float)(cnt < 1 ? 1 : cnt) + d_q[v] + pb[0];
}

__global__ void score2_k(const float* __restrict__ pb,
                         const int* __restrict__ perm,
                         const int* __restrict__ map, int n) {
    int i = blockIdx.x * blockDim.x + threadIdx.x;
    if (i >= n) return;
    int v = perm[i];
    const int* col = &d_cols[(size_t)v * CAP];
    int cnt = d_fill[v];
    float s = 0.f; int c = 0;
    for (int e = 0; e < cnt; e++) {
        int m = map[col[e]];
        if (m >= 0) { s += d_p[m]; c++; }
    }
    d_score[i] = s / (float)(c < 1 ? 1 : c) + d_q[i] + pb[0];
}

// ---------------- per-graph top-k (bitonic 512) ----------------
__global__ void __launch_bounds__(512) topk_k(int npg, int k, int* __restrict__ perm_out) {
    __shared__ float sc[512];
    __shared__ int   id[512];
    int b = blockIdx.x, tid = threadIdx.x;
    if (tid < npg) {
        sc[tid] = d_score[b * npg + tid];
        id[tid] = b * npg + tid;
    } else {
        sc[tid] = -INFINITY;
        id[tid] = 0x7FFFFFFF;
    }
    __syncthreads();
    for (int kk = 2; kk <= 512; kk <<= 1) {
        for (int j = kk >> 1; j > 0; j >>= 1) {
            int i = tid, ixj = i ^ j;
            if (ixj > i) {
                float s1 = sc[i], s2 = sc[ixj];
                int i1 = id[i], i2 = id[ixj];
                bool beforeIxj = (s2 > s1) || (s2 == s1 && i2 < i1);
                bool up = ((i & kk) == 0);
                if (up ? beforeIxj : !beforeIxj) {
                    sc[i] = s2; sc[ixj] = s1;
                    id[i] = i2; id[ixj] = i1;
                }
            }
            __syncthreads();
        }
    }
    if (tid < k) {
        perm_out[b * k + tid] = id[tid];
        d_tsc[b * k + tid] = tanhf(sc[tid]);
    }
}

__global__ void compose_k() {
    int i = blockIdx.x * blockDim.x + threadIdx.x;
    if (i >= NAL2) return;
    int i1 = d_perm2s[i];
    int o = d_perm1[i1];
    d_permO2[i] = o;
    d_map2[o] = i;
}

__global__ void compact_k(int srcsel, int dstsel, const int* __restrict__ perm,
                          int n, int* __restrict__ map_or_null) {
    int g = blockIdx.x * blockDim.x + threadIdx.x;
    int w = g >> 5, lane = g & 31;
    if (w >= n) return;
    int src_row = perm[w];
    if (map_or_null && lane == 0) map_or_null[src_row] = w;
    float t = d_tsc[w];
    const float* S = selX(nullptr, srcsel);
    float* D = selXw(dstsel);
    float4 v = ((const float4*)(S + (size_t)src_row * HDIM))[lane];
    v.x *= t; v.y *= t; v.z *= t; v.w *= t;
    ((float4*)(D + (size_t)w * HDIM))[lane] = v;
}

// ---------------- MLP head ----------------
__global__ void head_k(const float* __restrict__ l1w, const float* __restrict__ l1b,
                       const float* __restrict__ l2w, const float* __restrict__ l2b,
                       float* __restrict__ out) {
    int b = blockIdx.x, h = threadIdx.x;
    float acc = l1b[h];
#pragma unroll 2
    for (int l = 0; l < NLAY; l++) {
        const float* xr = &d_xs[(l * BGRAPH + b) * HDIM];
#pragma unroll 8
        for (int kk = 0; kk < HDIM; kk++) {
            acc += xr[kk] * l1w[(l * HDIM + kk) * HDIM + h];
        }
    }
    acc = fmaxf(acc, 0.f);
    __shared__ float s0[128], s1[128];
    s0[h] = acc * l2w[h * 2 + 0];
    s1[h] = acc * l2w[h * 2 + 1];
    __syncthreads();
    for (int off = 64; off; off >>= 1) {
        if (h < off) { s0[h] += s0[h + off]; s1[h] += s1[h + off]; }
        __syncthreads();
    }
    if (h == 0) {
        float l0 = s0[0] + l2b[0];
        float l1 = s1[0] + l2b[1];
        float m = fmaxf(l0, l1);
        float lse = m + logf(expf(l0 - m) + expf(l1 - m));
        out[b * 2 + 0] = l0 - lse;
        out[b * 2 + 1] = l1 - lse;
    }
}

// ---------------- launch (gmean forked to a second stream) ----------------
static cudaStream_t g_s2;
static cudaEvent_t  g_evF[5], g_evJ[5];
static int g_streams_ready = 0;

extern "C" void kernel_launch(void* const* d_in, const int* in_sizes, int n_in,
                              void* d_out, int out_size) {
    const float* x    = (const float*)d_in[0];
    const int*   ei   = (const int*)d_in[1];
    const float* c1wr = (const float*)d_in[3];
    const float* c1ws = (const float*)d_in[4];
    const float* c1b  = (const float*)d_in[5];
    const float* cwr  = (const float*)d_in[6];
    const float* cws  = (const float*)d_in[7];
    const float* cb   = (const float*)d_in[8];
    const float* pwr  = (const float*)d_in[9];
    const float* pws  = (const float*)d_in[10];
    const float* pb   = (const float*)d_in[11];
    const float* l1w  = (const float*)d_in[12];
    const float* l1b  = (const float*)d_in[13];
    const float* l2w  = (const float*)d_in[14];
    const float* l2b  = (const float*)d_in[15];
    float* out = (float*)d_out;

    const int WPB = 256;

    if (!g_streams_ready) {   // first call is the uncaptured correctness run
        cudaStreamCreateWithFlags(&g_s2, cudaStreamNonBlocking);
        for (int i = 0; i < 5; i++) {
            cudaEventCreateWithFlags(&g_evF[i], cudaEventDisableTiming);
            cudaEventCreateWithFlags(&g_evJ[i], cudaEventDisableTiming);
        }
        g_streams_ready = 1;
    }

    int *perm1, *perm2s, *permO2, *map1, *map2;
    cudaGetSymbolAddress((void**)&perm1, d_perm1);
    cudaGetSymbolAddress((void**)&perm2s, d_perm2s);
    cudaGetSymbolAddress((void**)&permO2, d_permO2);
    cudaGetSymbolAddress((void**)&map1, d_map1);
    cudaGetSymbolAddress((void**)&map2, d_map2);

    // bucket build
    init_k<<<NNODE / WPB, WPB>>>();
    scatter_k<<<NEDGE / WPB, WPB>>>(ei);

    // conv1: x -> XA
    agg_full_g<<<NSM, 1024>>>(x, 0);
    gemm_k<<<NNODE / 128, 256>>>(x, 0, 1, c1wr, c1ws, c1b);
    cudaEventRecord(g_evF[0], 0);
    cudaStreamWaitEvent(g_s2, g_evF[0], 0);
    gmean_k<<<BGRAPH, 512, 0, g_s2>>>(x, 1, 0, NPG0, 1.0f / 400.0f);   // reads XA
    cudaEventRecord(g_evJ[0], g_s2);

    // conv2: XA -> XB
    agg_full_g<<<NSM, 1024>>>(x, 1);
    gemm_k<<<NNODE / 128, 256>>>(x, 1, 2, cwr + 0 * HDIM * HDIM, cws + 0 * HDIM * HDIM, cb + 0 * HDIM);
    cudaEventRecord(g_evF[1], 0);
    cudaStreamWaitEvent(g_s2, g_evF[1], 0);
    gmean_k<<<BGRAPH, 512, 0, g_s2>>>(x, 2, 1, NPG0, 1.0f / 400.0f);   // reads XB
    cudaEventRecord(g_evJ[1], g_s2);

    // pool1: XB -> space1 (compact XB -> XA); XA overwritten -> join gmean0 first
    dots_k<<<NNODE / 8, WPB>>>(x, 2, NNODE, pwr + 0 * HDIM, pws + 0 * HDIM);
    score1_k<<<NNODE / WPB, WPB>>>(pb + 0);
    topk_k<<<BGRAPH, 512>>>(NPG0, NPG1, perm1);
    cudaStreamWaitEvent(0, g_evJ[0], 0);
    compact_k<<<NAL1 / 8, WPB>>>(2, 1, perm1, NAL1, map1);

    // conv3 (space1): XA -> XB; XB overwritten -> join gmean1 first
    agg_c_g<<<NSM, 1024>>>(1, NPG1, perm1, map1);
    cudaStreamWaitEvent(0, g_evJ[1], 0);
    gemm_k<<<NAL1 / 128, 256>>>(x, 1, 2, cwr + 1 * HDIM * HDIM, cws + 1 * HDIM * HDIM, cb + 1 * HDIM);
    cudaEventRecord(g_evF[2], 0);
    cudaStreamWaitEvent(g_s2, g_evF[2], 0);
    gmean_k<<<BGRAPH, 512, 0, g_s2>>>(x, 2, 2, NPG1, 1.0f / 320.0f);   // reads XB
    cudaEventRecord(g_evJ[2], g_s2);

    // conv4 (space1): XB -> XA
    agg_c_g<<<NSM, 1024>>>(2, NPG1, perm1, map1);
    gemm_k<<<NAL1 / 128, 256>>>(x, 2, 1, cwr + 2 * HDIM * HDIM, cws + 2 * HDIM * HDIM, cb + 2 * HDIM);
    cudaEventRecord(g_evF[3], 0);
    cudaStreamWaitEvent(g_s2, g_evF[3], 0);
    gmean_k<<<BGRAPH, 512, 0, g_s2>>>(x, 1, 3, NPG1, 1.0f / 320.0f);   // reads XA
    cudaEventRecord(g_evJ[3], g_s2);

    // pool2: XA -> space2 (compact XA -> XB); XB overwritten -> join gmean2 first
    dots_k<<<NAL1 / 8, WPB>>>(x, 1, NAL1, pwr + 1 * HDIM, pws + 1 * HDIM);
    score2_k<<<NAL1 / WPB, WPB>>>(pb + 1, perm1, map1, NAL1);
    topk_k<<<BGRAPH, 512>>>(NPG1, NPG2, perm2s);
    compose_k<<<NAL2 / WPB, WPB>>>();
    cudaStreamWaitEvent(0, g_evJ[2], 0);
    compact_k<<<NAL2 / 8, WPB>>>(1, 2, perm2s, NAL2, nullptr);

    // conv5 (space2): XB -> XA; XA overwritten -> join gmean3 first
    agg_c_g<<<NSM, 1024>>>(2, NPG2, permO2, map2);
    cudaStreamWaitEvent(0, g_evJ[3], 0);
    gemm_k<<<NAL2 / 128, 256>>>(x, 2, 1, cwr + 3 * HDIM * HDIM, cws + 3 * HDIM * HDIM, cb + 3 * HDIM);
    cudaEventRecord(g_evF[4], 0);
    cudaStreamWaitEvent(g_s2, g_evF[4], 0);
    gmean_k<<<BGRAPH, 512, 0, g_s2>>>(x, 1, 4, NPG2, 1.0f / 256.0f);   // reads XA
    cudaEventRecord(g_evJ[4], g_s2);

    // head: needs all gmeans
    cudaStreamWaitEvent(0, g_evJ[4], 0);
    head_k<<<BGRAPH, HDIM>>>(l1w, l1b, l2w, l2b, out);
}

// round 16
// speedup vs baseline: 1.1241x; 1.0789x over previous
#include <cuda_runtime.h>
#include <math.h>

#define BGRAPH 256
#define NPG0   400
#define DEG    16
#define HDIM   128
#define NLAY   5
#define NNODE  (BGRAPH*NPG0)      /* 102400 */
#define NEDGE  (NNODE*DEG)        /* 1638400 */
#define NPG1   320
#define NPG2   256
#define NAL1   (BGRAPH*NPG1)      /* 81920 */
#define NAL2   (BGRAPH*NPG2)      /* 65536 */
#define NSM    148
#define CAP    64                 /* bucket capacity per node (P(deg>64) ~ 0) */

// ---------------- device scratch (static, allowed) ----------------
__device__ float d_XA[(size_t)NNODE*HDIM];
__device__ float d_XB[(size_t)NNODE*HDIM];
__device__ float d_MEAN[(size_t)NNODE*HDIM];
__device__ int   d_fill[NNODE];
__device__ int   d_cols[(size_t)NNODE*CAP];
__device__ float d_p[NNODE];
__device__ float d_q[NNODE];
__device__ float d_score[NNODE];
__device__ float d_tsc[NAL1];
__device__ float d_xs[NLAY*BGRAPH*HDIM];
__device__ int   d_perm1[NAL1];
__device__ int   d_perm2s[NAL2];
__device__ int   d_permO2[NAL2];
__device__ int   d_map1[NNODE];
__device__ int   d_map2[NNODE];

__device__ __forceinline__ const float* selX(const float* xext, int sel) {
    return sel == 0 ? xext : (sel == 1 ? d_XA : d_XB);
}
__device__ __forceinline__ float* selXw(int sel) {
    return sel == 1 ? d_XA : d_XB;
}

// packed fp32x2 (sm_103a FFMA2, exact fp32 semantics)
__device__ __forceinline__ void fma2(unsigned long long& d,
                                     unsigned long long a,
                                     unsigned long long b) {
    asm("fma.rn.f32x2 %0, %1, %2, %0;" : "+l"(d) : "l"(a), "l"(b));
}
__device__ __forceinline__ float2 unpack2(unsigned long long v) {
    float2 r;
    asm("mov.b64 {%0, %1}, %2;" : "=f"(r.x), "=f"(r.y) : "l"(v));
    return r;
}

// ---------------- bucket build ----------------
__global__ void init_k() {
    int v = blockIdx.x * blockDim.x + threadIdx.x;
    if (v < NNODE) { d_fill[v] = 0; d_map1[v] = -1; d_map2[v] = -1; }
}

__global__ void scatter_k(const int* __restrict__ ei) {
    int e = blockIdx.x * blockDim.x + threadIdx.x;
    if (e < NEDGE) {
        int dst = ei[NEDGE + e];
        int pos = atomicAdd(&d_fill[dst], 1);
        d_cols[(size_t)dst * CAP + pos] = ei[e];
    }
}

// ---------------- mean aggregation, graph-per-CTA (L1-resident) --------------
__global__ void __launch_bounds__(1024, 1) agg_full_g(const float* __restrict__ xext,
                                                      int xsel) {
    const float* X = selX(xext, xsel);
    int w = threadIdx.x >> 5, lane = threadIdx.x & 31;
    for (int b = blockIdx.x; b < BGRAPH; b += gridDim.x) {
        for (int r = w; r < NPG0; r += 32) {
            int v = b * NPG0 + r;
            const int* col = &d_cols[(size_t)v * CAP];
            int cnt = d_fill[v];
            float4 acc = make_float4(0.f, 0.f, 0.f, 0.f);
            for (int e = 0; e < cnt; e++) {
                int u = col[e];
                float4 xv = ((const float4*)(X + (size_t)u * HDIM))[lane];
                acc.x += xv.x; acc.y += xv.y; acc.z += xv.z; acc.w += xv.w;
            }
            float inv = 1.0f / (float)(cnt < 1 ? 1 : cnt);
            acc.x *= inv; acc.y *= inv; acc.z *= inv; acc.w *= inv;
            ((float4*)(d_MEAN + (size_t)v * HDIM))[lane] = acc;
        }
    }
}

__global__ void __launch_bounds__(1024, 1) agg_c_g(int xsel, int npg,
                                                   const int* __restrict__ perm,
                                                   const int* __restrict__ map) {
    const float* X = selX(nullptr, xsel);
    int w = threadIdx.x >> 5, lane = threadIdx.x & 31;
    for (int b = blockIdx.x; b < BGRAPH; b += gridDim.x) {
        for (int r = w; r < npg; r += 32) {
            int i = b * npg + r;
            int v = perm[i];
            const int* col = &d_cols[(size_t)v * CAP];
            int cnt = d_fill[v];
            float4 acc = make_float4(0.f, 0.f, 0.f, 0.f);
            int c = 0;
            for (int e = 0; e < cnt; e++) {
                int m = map[col[e]];
                if (m >= 0) {
                    c++;
                    float4 xv = ((const float4*)(X + (size_t)m * HDIM))[lane];
                    acc.x += xv.x; acc.y += xv.y; acc.z += xv.z; acc.w += xv.w;
                }
            }
            float inv = 1.0f / (float)(c < 1 ? 1 : c);
            acc.x *= inv; acc.y *= inv; acc.z *= inv; acc.w *= inv;
            ((float4*)(d_MEAN + (size_t)i * HDIM))[lane] = acc;
        }
    }
}

// ---------------- fused conv GEMM: OUT = relu(MEAN@Wr + X@Ws + b) ------------
// FFMA2, single-buffered, 128 threads / 64-row tile -> 4 CTAs/SM (4 independent
// stage-sync-compute pipelines per SM). Inner loop identical to the proven one.
#define AS2_STRIDE 132
__global__ void __launch_bounds__(128, 4) gemm_k(const float* __restrict__ xext,
                                                 int xsel, int osel,
                                                 const float* __restrict__ Wr,
                                                 const float* __restrict__ Ws,
                                                 const float* __restrict__ bias) {
    __shared__ __align__(16) float As2[16][AS2_STRIDE];  // duplicated A, 64 rows
    __shared__ __align__(16) float Bs[16][128];
    int row0 = blockIdx.x * 64;
    int tid = threadIdx.x;
    int tx = tid & 15, ty = tid >> 4;   // ty 0..7 -> 64 rows

    unsigned long long acc[8][4];
#pragma unroll
    for (int i = 0; i < 8; i++)
#pragma unroll
        for (int j = 0; j < 4; j++) acc[i][j] = 0ull;

    const float* Xin = selX(xext, xsel);
    for (int phase = 0; phase < 2; ++phase) {
        const float* A = phase ? Xin : d_MEAN;
        const float* W = phase ? Ws : Wr;
        for (int k0 = 0; k0 < 128; k0 += 16) {
            // A: 64 rows x 16 k = 1024 elems / 128 thr = 8 each
#pragma unroll
            for (int r = 0; r < 8; r++) {
                int idx = tid + r * 128;
                int m = idx >> 4, kk = idx & 15;
                float v = A[(size_t)(row0 + m) * HDIM + k0 + kk];
                unsigned saddr = (unsigned)__cvta_generic_to_shared(&As2[kk][2 * m]);
                asm volatile("st.shared.v2.f32 [%0], {%1, %1};" :: "r"(saddr), "f"(v));
            }
            // B: 16 x 128 = 2048 elems / 128 thr = 16 each
#pragma unroll
            for (int r = 0; r < 16; r++) {
                int idx = tid + r * 128;
                int kk = idx >> 7, n = idx & 127;
                Bs[kk][n] = W[(k0 + kk) * HDIM + n];
            }
            __syncthreads();
#pragma unroll
            for (int kk = 0; kk < 16; kk++) {
                const ulonglong2* pa = (const ulonglong2*)&As2[kk][16 * ty];
                ulonglong2 A0 = pa[0], A1 = pa[1], A2 = pa[2], A3 = pa[3];
                const ulonglong2* pb = (const ulonglong2*)&Bs[kk][8 * tx];
                ulonglong2 B0 = pb[0], B1 = pb[1];
                unsigned long long a[8] = {A0.x, A0.y, A1.x, A1.y, A2.x, A2.y, A3.x, A3.y};
                unsigned long long b[4] = {B0.x, B0.y, B1.x, B1.y};
#pragma unroll
                for (int i = 0; i < 8; i++)
#pragma unroll
                    for (int j = 0; j < 4; j++) fma2(acc[i][j], a[i], b[j]);
            }
            __syncthreads();
        }
    }
    float* OUT = selXw(osel);
    float4 bv0 = *(const float4*)&bias[tx * 8];
    float4 bv1 = *(const float4*)&bias[tx * 8 + 4];
#pragma unroll
    for (int i = 0; i < 8; i++) {
        int gr = row0 + ty * 8 + i;
        float2 v0 = unpack2(acc[i][0]);
        float2 v1 = unpack2(acc[i][1]);
        float2 v2 = unpack2(acc[i][2]);
        float2 v3 = unpack2(acc[i][3]);
        float4 o0, o1;
        o0.x = fmaxf(v0.x + bv0.x, 0.f);
        o0.y = fmaxf(v0.y + bv0.y, 0.f);
        o0.z = fmaxf(v1.x + bv0.z, 0.f);
        o0.w = fmaxf(v1.y + bv0.w, 0.f);
        o1.x = fmaxf(v2.x + bv1.x, 0.f);
        o1.y = fmaxf(v2.y + bv1.y, 0.f);
        o1.z = fmaxf(v3.x + bv1.z, 0.f);
        o1.w = fmaxf(v3.y + bv1.w, 0.f);
        float4* orow = (float4*)(OUT + (size_t)gr * HDIM + tx * 8);
        orow[0] = o0;
        orow[1] = o1;
    }
}

// ---------------- per-graph mean pool (contiguous rows, no masks) ------------
__global__ void __launch_bounds__(512) gmean_k(const float* __restrict__ xext,
                                               int xsel, int layer, int npg, float inv) {
    __shared__ float red[4][128];
    int b = blockIdx.x;
    int h = threadIdx.x & 127;
    int g = threadIdx.x >> 7;
    const float* X = selX(xext, xsel);
    int base = b * npg;
    float s = 0.f;
    for (int r = g; r < npg; r += 4)
        s += X[(size_t)(base + r) * HDIM + h];
    red[g][h] = s;
    __syncthreads();
    if (g == 0) {
        float t = red[0][h] + red[1][h] + red[2][h] + red[3][h];
        d_xs[(layer * BGRAPH + b) * HDIM + h] = t * inv;
    }
}

// ---------------- pool scoring ----------------
__global__ void dots_k(const float* __restrict__ xext, int xsel, int n,
                       const float* __restrict__ wr, const float* __restrict__ ws) {
    int g = blockIdx.x * blockDim.x + threadIdx.x;
    int w = g >> 5, lane = g & 31;
    if (w >= n) return;
    const float* X = selX(xext, xsel);
    float4 xv = ((const float4*)(X + (size_t)w * HDIM))[lane];
    float4 a = ((const float4*)wr)[lane];
    float4 b = ((const float4*)ws)[lane];
    float pp = xv.x * a.x + xv.y * a.y + xv.z * a.z + xv.w * a.w;
    float qq = xv.x * b.x + xv.y * b.y + xv.z * b.z + xv.w * b.w;
#pragma unroll
    for (int o = 16; o; o >>= 1) {
        pp += __shfl_down_sync(0xFFFFFFFFu, pp, o);
        qq += __shfl_down_sync(0xFFFFFFFFu, qq, o);
    }
    if (lane == 0) { d_p[w] = pp; d_q[w] = qq; }
}

__global__ void score1_k(const float* __restrict__ pb) {
    int v = blockIdx.x * blockDim.x + threadIdx.x;
    if (v >= NNODE) return;
    const int* col = &d_cols[(size_t)v * CAP];
    int cnt = d_fill[v];
    float s = 0.f;
    for (int e = 0; e < cnt; e++) s += d_p[col[e]];
    d_score[v] = s / (float)(cnt < 1 ? 1 : cnt) + d_q[v] + pb[0];
}

__global__ void score2_k(const float* __restrict__ pb,
                         const int* __restrict__ perm,
                         const int* __restrict__ map, int n) {
    int i = blockIdx.x * blockDim.x + threadIdx.x;
    if (i >= n) return;
    int v = perm[i];
    const int* col = &d_cols[(size_t)v * CAP];
    int cnt = d_fill[v];
    float s = 0.f; int c = 0;
    for (int e = 0; e < cnt; e++) {
        int m = map[col[e]];
        if (m >= 0) { s += d_p[m]; c++; }
    }
    d_score[i] = s / (float)(c < 1 ? 1 : c) + d_q[i] + pb[0];
}

// ---------------- per-graph top-k (bitonic 512) ----------------
__global__ void __launch_bounds__(512) topk_k(int npg, int k, int* __restrict__ perm_out) {
    __shared__ float sc[512];
    __shared__ int   id[512];
    int b = blockIdx.x, tid = threadIdx.x;
    if (tid < npg) {
        sc[tid] = d_score[b * npg + tid];
        id[tid] = b * npg + tid;
    } else {
        sc[tid] = -INFINITY;
        id[tid] = 0x7FFFFFFF;
    }
    __syncthreads();
    for (int kk = 2; kk <= 512; kk <<= 1) {
        for (int j = kk >> 1; j > 0; j >>= 1) {
            int i = tid, ixj = i ^ j;
            if (ixj > i) {
                float s1 = sc[i], s2 = sc[ixj];
                int i1 = id[i], i2 = id[ixj];
                bool beforeIxj = (s2 > s1) || (s2 == s1 && i2 < i1);
                bool up = ((i & kk) == 0);
                if (up ? beforeIxj : !beforeIxj) {
                    sc[i] = s2; sc[ixj] = s1;
                    id[i] = i2; id[ixj] = i1;
                }
            }
            __syncthreads();
        }
    }
    if (tid < k) {
        perm_out[b * k + tid] = id[tid];
        d_tsc[b * k + tid] = tanhf(sc[tid]);
    }
}

__global__ void compose_k() {
    int i = blockIdx.x * blockDim.x + threadIdx.x;
    if (i >= NAL2) return;
    int i1 = d_perm2s[i];
    int o = d_perm1[i1];
    d_permO2[i] = o;
    d_map2[o] = i;
}

__global__ void compact_k(int srcsel, int dstsel, const int* __restrict__ perm,
                          int n, int* __restrict__ map_or_null) {
    int g = blockIdx.x * blockDim.x + threadIdx.x;
    int w = g >> 5, lane = g & 31;
    if (w >= n) return;
    int src_row = perm[w];
    if (map_or_null && lane == 0) map_or_null[src_row] = w;
    float t = d_tsc[w];
    const float* S = selX(nullptr, srcsel);
    float* D = selXw(dstsel);
    float4 v = ((const float4*)(S + (size_t)src_row * HDIM))[lane];
    v.x *= t; v.y *= t; v.z *= t; v.w *= t;
    ((float4*)(D + (size_t)w * HDIM))[lane] = v;
}

// ---------------- MLP head ----------------
__global__ void head_k(const float* __restrict__ l1w, const float* __restrict__ l1b,
                       const float* __restrict__ l2w, const float* __restrict__ l2b,
                       float* __restrict__ out) {
    int b = blockIdx.x, h = threadIdx.x;
    float acc = l1b[h];
#pragma unroll 2
    for (int l = 0; l < NLAY; l++) {
        const float* xr = &d_xs[(l * BGRAPH + b) * HDIM];
#pragma unroll 8
        for (int kk = 0; kk < HDIM; kk++) {
            acc += xr[kk] * l1w[(l * HDIM + kk) * HDIM + h];
        }
    }
    acc = fmaxf(acc, 0.f);
    __shared__ float s0[128], s1[128];
    s0[h] = acc * l2w[h * 2 + 0];
    s1[h] = acc * l2w[h * 2 + 1];
    __syncthreads();
    for (int off = 64; off; off >>= 1) {
        if (h < off) { s0[h] += s0[h + off]; s1[h] += s1[h + off]; }
        __syncthreads();
    }
    if (h == 0) {
        float l0 = s0[0] + l2b[0];
        float l1 = s1[0] + l2b[1];
        float m = fmaxf(l0, l1);
        float lse = m + logf(expf(l0 - m) + expf(l1 - m));
        out[b * 2 + 0] = l0 - lse;
        out[b * 2 + 1] = l1 - lse;
    }
}

// ---------------- launch (gmean forked to a second stream) ----------------
static cudaStream_t g_s2;
static cudaEvent_t  g_evF[5], g_evJ[5];
static int g_streams_ready = 0;

extern "C" void kernel_launch(void* const* d_in, const int* in_sizes, int n_in,
                              void* d_out, int out_size) {
    const float* x    = (const float*)d_in[0];
    const int*   ei   = (const int*)d_in[1];
    const float* c1wr = (const float*)d_in[3];
    const float* c1ws = (const float*)d_in[4];
    const float* c1b  = (const float*)d_in[5];
    const float* cwr  = (const float*)d_in[6];
    const float* cws  = (const float*)d_in[7];
    const float* cb   = (const float*)d_in[8];
    const float* pwr  = (const float*)d_in[9];
    const float* pws  = (const float*)d_in[10];
    const float* pb   = (const float*)d_in[11];
    const float* l1w  = (const float*)d_in[12];
    const float* l1b  = (const float*)d_in[13];
    const float* l2w  = (const float*)d_in[14];
    const float* l2b  = (const float*)d_in[15];
    float* out = (float*)d_out;

    const int WPB = 256;

    if (!g_streams_ready) {   // first call is the uncaptured correctness run
        cudaStreamCreateWithFlags(&g_s2, cudaStreamNonBlocking);
        for (int i = 0; i < 5; i++) {
            cudaEventCreateWithFlags(&g_evF[i], cudaEventDisableTiming);
            cudaEventCreateWithFlags(&g_evJ[i], cudaEventDisableTiming);
        }
        g_streams_ready = 1;
    }

    int *perm1, *perm2s, *permO2, *map1, *map2;
    cudaGetSymbolAddress((void**)&perm1, d_perm1);
    cudaGetSymbolAddress((void**)&perm2s, d_perm2s);
    cudaGetSymbolAddress((void**)&permO2, d_permO2);
    cudaGetSymbolAddress((void**)&map1, d_map1);
    cudaGetSymbolAddress((void**)&map2, d_map2);

    // bucket build
    init_k<<<NNODE / WPB, WPB>>>();
    scatter_k<<<NEDGE / WPB, WPB>>>(ei);

    // conv1: x -> XA
    agg_full_g<<<NSM, 1024>>>(x, 0);
    gemm_k<<<NNODE / 64, 128>>>(x, 0, 1, c1wr, c1ws, c1b);
    cudaEventRecord(g_evF[0], 0);
    cudaStreamWaitEvent(g_s2, g_evF[0], 0);
    gmean_k<<<BGRAPH, 512, 0, g_s2>>>(x, 1, 0, NPG0, 1.0f / 400.0f);   // reads XA
    cudaEventRecord(g_evJ[0], g_s2);

    // conv2: XA -> XB
    agg_full_g<<<NSM, 1024>>>(x, 1);
    gemm_k<<<NNODE / 64, 128>>>(x, 1, 2, cwr + 0 * HDIM * HDIM, cws + 0 * HDIM * HDIM, cb + 0 * HDIM);
    cudaEventRecord(g_evF[1], 0);
    cudaStreamWaitEvent(g_s2, g_evF[1], 0);
    gmean_k<<<BGRAPH, 512, 0, g_s2>>>(x, 2, 1, NPG0, 1.0f / 400.0f);   // reads XB
    cudaEventRecord(g_evJ[1], g_s2);

    // pool1: XB -> space1 (compact XB -> XA); XA overwritten -> join gmean0 first
    dots_k<<<NNODE / 8, WPB>>>(x, 2, NNODE, pwr + 0 * HDIM, pws + 0 * HDIM);
    score1_k<<<NNODE / WPB, WPB>>>(pb + 0);
    topk_k<<<BGRAPH, 512>>>(NPG0, NPG1, perm1);
    cudaStreamWaitEvent(0, g_evJ[0], 0);
    compact_k<<<NAL1 / 8, WPB>>>(2, 1, perm1, NAL1, map1);

    // conv3 (space1): XA -> XB; XB overwritten -> join gmean1 first
    agg_c_g<<<NSM, 1024>>>(1, NPG1, perm1, map1);
    cudaStreamWaitEvent(0, g_evJ[1], 0);
    gemm_k<<<NAL1 / 64, 128>>>(x, 1, 2, cwr + 1 * HDIM * HDIM, cws + 1 * HDIM * HDIM, cb + 1 * HDIM);
    cudaEventRecord(g_evF[2], 0);
    cudaStreamWaitEvent(g_s2, g_evF[2], 0);
    gmean_k<<<BGRAPH, 512, 0, g_s2>>>(x, 2, 2, NPG1, 1.0f / 320.0f);   // reads XB
    cudaEventRecord(g_evJ[2], g_s2);

    // conv4 (space1): XB -> XA
    agg_c_g<<<NSM, 1024>>>(2, NPG1, perm1, map1);
    gemm_k<<<NAL1 / 64, 128>>>(x, 2, 1, cwr + 2 * HDIM * HDIM, cws + 2 * HDIM * HDIM, cb + 2 * HDIM);
    cudaEventRecord(g_evF[3], 0);
    cudaStreamWaitEvent(g_s2, g_evF[3], 0);
    gmean_k<<<BGRAPH, 512, 0, g_s2>>>(x, 1, 3, NPG1, 1.0f / 320.0f);   // reads XA
    cudaEventRecord(g_evJ[3], g_s2);

    // pool2: XA -> space2 (compact XA -> XB); XB overwritten -> join gmean2 first
    dots_k<<<NAL1 / 8, WPB>>>(x, 1, NAL1, pwr + 1 * HDIM, pws + 1 * HDIM);
    score2_k<<<NAL1 / WPB, WPB>>>(pb + 1, perm1, map1, NAL1);
    topk_k<<<BGRAPH, 512>>>(NPG1, NPG2, perm2s);
    compose_k<<<NAL2 / WPB, WPB>>>();
    cudaStreamWaitEvent(0, g_evJ[2], 0);
    compact_k<<<NAL2 / 8, WPB>>>(1, 2, perm2s, NAL2, nullptr);

    // conv5 (space2): XB -> XA; XA overwritten -> join gmean3 first
    agg_c_g<<<NSM, 1024>>>(2, NPG2, permO2, map2);
    cudaStreamWaitEvent(0, g_evJ[3], 0);
    gemm_k<<<NAL2 / 64, 128>>>(x, 2, 1, cwr + 3 * HDIM * HDIM, cws + 3 * HDIM * HDIM, cb + 3 * HDIM);
    cudaEventRecord(g_evF[4], 0);
    cudaStreamWaitEvent(g_s2, g_evF[4], 0);
    gmean_k<<<BGRAPH, 512, 0, g_s2>>>(x, 1, 4, NPG2, 1.0f / 256.0f);   // reads XA
    cudaEventRecord(g_evJ[4], g_s2);

    // head: needs all gmeans
    cudaStreamWaitEvent(0, g_evJ[4], 0);
    head_k<<<BGRAPH, HDIM>>>(l1w, l1b, l2w, l2b, out);
}

// round 17
// speedup vs baseline: 1.1280x; 1.0035x over previous
#include <cuda_runtime.h>
#include <math.h>

#define BGRAPH 256
#define NPG0   400
#define DEG    16
#define HDIM   128
#define NLAY   5
#define NNODE  (BGRAPH*NPG0)      /* 102400 */
#define NEDGE  (NNODE*DEG)        /* 1638400 */
#define NPG1   320
#define NPG2   256
#define NAL1   (BGRAPH*NPG1)      /* 81920 */
#define NAL2   (BGRAPH*NPG2)      /* 65536 */
#define NSM    148
#define CAP    64                 /* bucket capacity per node (P(deg>64) ~ 0) */

// ---------------- device scratch (static, allowed) ----------------
__device__ float d_XA[(size_t)NNODE*HDIM];
__device__ float d_XB[(size_t)NNODE*HDIM];
__device__ float d_MEAN[(size_t)NNODE*HDIM];
__device__ int   d_fill[NNODE];
__device__ int   d_cols[(size_t)NNODE*CAP];
__device__ float d_p[NNODE];
__device__ float d_q[NNODE];
__device__ float d_score[NNODE];
__device__ float d_tsc[NAL1];
__device__ float d_xs[NLAY*BGRAPH*HDIM];
__device__ int   d_perm1[NAL1];
__device__ int   d_perm2s[NAL2];
__device__ int   d_permO2[NAL2];
__device__ int   d_map1[NNODE];
__device__ int   d_map2[NNODE];

__device__ __forceinline__ const float* selX(const float* xext, int sel) {
    return sel == 0 ? xext : (sel == 1 ? d_XA : d_XB);
}
__device__ __forceinline__ float* selXw(int sel) {
    return sel == 1 ? d_XA : d_XB;
}

// packed fp32x2 (sm_103a FFMA2, exact fp32 semantics)
__device__ __forceinline__ void fma2(unsigned long long& d,
                                     unsigned long long a,
                                     unsigned long long b) {
    asm("fma.rn.f32x2 %0, %1, %2, %0;" : "+l"(d) : "l"(a), "l"(b));
}
__device__ __forceinline__ float2 unpack2(unsigned long long v) {
    float2 r;
    asm("mov.b64 {%0, %1}, %2;" : "=f"(r.x), "=f"(r.y) : "l"(v));
    return r;
}

// ---------------- bucket build ----------------
__global__ void init_k() {
    int v = blockIdx.x * blockDim.x + threadIdx.x;
    if (v < NNODE) { d_fill[v] = 0; d_map1[v] = -1; d_map2[v] = -1; }
}

__global__ void scatter_k(const int* __restrict__ ei) {
    int e = blockIdx.x * blockDim.x + threadIdx.x;
    if (e < NEDGE) {
        int dst = ei[NEDGE + e];
        int pos = atomicAdd(&d_fill[dst], 1);
        d_cols[(size_t)dst * CAP + pos] = ei[e];
    }
}

// ---------------- mean aggregation, graph-per-CTA (L1-resident) --------------
__global__ void __launch_bounds__(1024, 1) agg_full_g(const float* __restrict__ xext,
                                                      int xsel) {
    const float* X = selX(xext, xsel);
    int w = threadIdx.x >> 5, lane = threadIdx.x & 31;
    for (int b = blockIdx.x; b < BGRAPH; b += gridDim.x) {
        for (int r = w; r < NPG0; r += 32) {
            int v = b * NPG0 + r;
            const int* col = &d_cols[(size_t)v * CAP];
            int cnt = d_fill[v];
            float4 acc = make_float4(0.f, 0.f, 0.f, 0.f);
            for (int e = 0; e < cnt; e++) {
                int u = col[e];
                float4 xv = ((const float4*)(X + (size_t)u * HDIM))[lane];
                acc.x += xv.x; acc.y += xv.y; acc.z += xv.z; acc.w += xv.w;
            }
            float inv = 1.0f / (float)(cnt < 1 ? 1 : cnt);
            acc.x *= inv; acc.y *= inv; acc.z *= inv; acc.w *= inv;
            ((float4*)(d_MEAN + (size_t)v * HDIM))[lane] = acc;
        }
    }
}

__global__ void __launch_bounds__(1024, 1) agg_c_g(int xsel, int npg,
                                                   const int* __restrict__ perm,
                                                   const int* __restrict__ map) {
    const float* X = selX(nullptr, xsel);
    int w = threadIdx.x >> 5, lane = threadIdx.x & 31;
    for (int b = blockIdx.x; b < BGRAPH; b += gridDim.x) {
        for (int r = w; r < npg; r += 32) {
            int i = b * npg + r;
            int v = perm[i];
            const int* col = &d_cols[(size_t)v * CAP];
            int cnt = d_fill[v];
            float4 acc = make_float4(0.f, 0.f, 0.f, 0.f);
            int c = 0;
            for (int e = 0; e < cnt; e++) {
                int m = map[col[e]];
                if (m >= 0) {
                    c++;
                    float4 xv = ((const float4*)(X + (size_t)m * HDIM))[lane];
                    acc.x += xv.x; acc.y += xv.y; acc.z += xv.z; acc.w += xv.w;
                }
            }
            float inv = 1.0f / (float)(c < 1 ? 1 : c);
            acc.x *= inv; acc.y *= inv; acc.z *= inv; acc.w *= inv;
            ((float4*)(d_MEAN + (size_t)i * HDIM))[lane] = acc;
        }
    }
}

// ---------------- fused conv GEMM: OUT = relu(MEAN@Wr + X@Ws + b) ------------
// FFMA2, single-buffered, 128 thr / 64-row tile / 4 CTAs per SM.
// Staging vectorized: A 2xLDG.128 + 8 dup st.v2; B 4xLDG.128 + 4xSTS.128.
#define AS2_STRIDE 132
__global__ void __launch_bounds__(128, 4) gemm_k(const float* __restrict__ xext,
                                                 int xsel, int osel,
                                                 const float* __restrict__ Wr,
                                                 const float* __restrict__ Ws,
                                                 const float* __restrict__ bias) {
    __shared__ __align__(16) float As2[16][AS2_STRIDE];  // duplicated A, 64 rows
    __shared__ __align__(16) float Bs[16][128];
    int row0 = blockIdx.x * 64;
    int tid = threadIdx.x;
    int tx = tid & 15, ty = tid >> 4;   // ty 0..7 -> 64 rows

    unsigned long long acc[8][4];
#pragma unroll
    for (int i = 0; i < 8; i++)
#pragma unroll
        for (int j = 0; j < 4; j++) acc[i][j] = 0ull;

    const float* Xin = selX(xext, xsel);
    for (int phase = 0; phase < 2; ++phase) {
        const float* A = phase ? Xin : d_MEAN;
        const float* W = phase ? Ws : Wr;
        for (int k0 = 0; k0 < 128; k0 += 16) {
            // A: 1024 floats = 256 float4; 2 per thread. m = q>>2, kg = (q&3)*4.
#pragma unroll
            for (int r = 0; r < 2; r++) {
                int q = tid + r * 128;
                int m = q >> 2, kg = (q & 3) * 4;
                float4 av = *(const float4*)(A + (size_t)(row0 + m) * HDIM + k0 + kg);
                unsigned sa = (unsigned)__cvta_generic_to_shared(&As2[kg][2 * m]);
                asm volatile("st.shared.v2.f32 [%0], {%1, %1};" :: "r"(sa), "f"(av.x));
                asm volatile("st.shared.v2.f32 [%0], {%1, %1};" :: "r"(sa + AS2_STRIDE * 4), "f"(av.y));
                asm volatile("st.shared.v2.f32 [%0], {%1, %1};" :: "r"(sa + 2 * AS2_STRIDE * 4), "f"(av.z));
                asm volatile("st.shared.v2.f32 [%0], {%1, %1};" :: "r"(sa + 3 * AS2_STRIDE * 4), "f"(av.w));
            }
            // B: 2048 floats = 512 float4; 4 per thread. kk = q>>5, n4 = (q&31)*4.
#pragma unroll
            for (int r = 0; r < 4; r++) {
                int q = tid + r * 128;
                int kk = q >> 5, n4 = (q & 31) * 4;
                float4 bv = *(const float4*)(W + (k0 + kk) * HDIM + n4);
                *(float4*)&Bs[kk][n4] = bv;
            }
            __syncthreads();
#pragma unroll
            for (int kk = 0; kk < 16; kk++) {
                const ulonglong2* pa = (const ulonglong2*)&As2[kk][16 * ty];
                ulonglong2 A0 = pa[0], A1 = pa[1], A2 = pa[2], A3 = pa[3];
                const ulonglong2* pb = (const ulonglong2*)&Bs[kk][8 * tx];
                ulonglong2 B0 = pb[0], B1 = pb[1];
                unsigned long long a[8] = {A0.x, A0.y, A1.x, A1.y, A2.x, A2.y, A3.x, A3.y};
                unsigned long long b[4] = {B0.x, B0.y, B1.x, B1.y};
#pragma unroll
                for (int i = 0; i < 8; i++)
#pragma unroll
                    for (int j = 0; j < 4; j++) fma2(acc[i][j], a[i], b[j]);
            }
            __syncthreads();
        }
    }
    float* OUT = selXw(osel);
    float4 bv0 = *(const float4*)&bias[tx * 8];
    float4 bv1 = *(const float4*)&bias[tx * 8 + 4];
#pragma unroll
    for (int i = 0; i < 8; i++) {
        int gr = row0 + ty * 8 + i;
        float2 v0 = unpack2(acc[i][0]);
        float2 v1 = unpack2(acc[i][1]);
        float2 v2 = unpack2(acc[i][2]);
        float2 v3 = unpack2(acc[i][3]);
        float4 o0, o1;
        o0.x = fmaxf(v0.x + bv0.x, 0.f);
        o0.y = fmaxf(v0.y + bv0.y, 0.f);
        o0.z = fmaxf(v1.x + bv0.z, 0.f);
        o0.w = fmaxf(v1.y + bv0.w, 0.f);
        o1.x = fmaxf(v2.x + bv1.x, 0.f);
        o1.y = fmaxf(v2.y + bv1.y, 0.f);
        o1.z = fmaxf(v3.x + bv1.z, 0.f);
        o1.w = fmaxf(v3.y + bv1.w, 0.f);
        float4* orow = (float4*)(OUT + (size_t)gr * HDIM + tx * 8);
        orow[0] = o0;
        orow[1] = o1;
    }
}

// ---------------- per-graph mean pool (contiguous rows, no masks) ------------
__global__ void __launch_bounds__(512) gmean_k(const float* __restrict__ xext,
                                               int xsel, int layer, int npg, float inv) {
    __shared__ float red[4][128];
    int b = blockIdx.x;
    int h = threadIdx.x & 127;
    int g = threadIdx.x >> 7;
    const float* X = selX(xext, xsel);
    int base = b * npg;
    float s = 0.f;
    for (int r = g; r < npg; r += 4)
        s += X[(size_t)(base + r) * HDIM + h];
    red[g][h] = s;
    __syncthreads();
    if (g == 0) {
        float t = red[0][h] + red[1][h] + red[2][h] + red[3][h];
        d_xs[(layer * BGRAPH + b) * HDIM + h] = t * inv;
    }
}

// ---------------- pool scoring ----------------
__global__ void dots_k(const float* __restrict__ xext, int xsel, int n,
                       const float* __restrict__ wr, const float* __restrict__ ws) {
    int g = blockIdx.x * blockDim.x + threadIdx.x;
    int w = g >> 5, lane = g & 31;
    if (w >= n) return;
    const float* X = selX(xext, xsel);
    float4 xv = ((const float4*)(X + (size_t)w * HDIM))[lane];
    float4 a = ((const float4*)wr)[lane];
    float4 b = ((const float4*)ws)[lane];
    float pp = xv.x * a.x + xv.y * a.y + xv.z * a.z + xv.w * a.w;
    float qq = xv.x * b.x + xv.y * b.y + xv.z * b.z + xv.w * b.w;
#pragma unroll
    for (int o = 16; o; o >>= 1) {
        pp += __shfl_down_sync(0xFFFFFFFFu, pp, o);
        qq += __shfl_down_sync(0xFFFFFFFFu, qq, o);
    }
    if (lane == 0) { d_p[w] = pp; d_q[w] = qq; }
}

__global__ void score1_k(const float* __restrict__ pb) {
    int v = blockIdx.x * blockDim.x + threadIdx.x;
    if (v >= NNODE) return;
    const int* col = &d_cols[(size_t)v * CAP];
    int cnt = d_fill[v];
    float s = 0.f;
    for (int e = 0; e < cnt; e++) s += d_p[col[e]];
    d_score[v] = s / (float)(cnt < 1 ? 1 : cnt) + d_q[v] + pb[0];
}

__global__ void score2_k(const float* __restrict__ pb,
                         const int* __restrict__ perm,
                         const int* __restrict__ map, int n) {
    int i = blockIdx.x * blockDim.x + threadIdx.x;
    if (i >= n) return;
    int v = perm[i];
    const int* col = &d_cols[(size_t)v * CAP];
    int cnt = d_fill[v];
    float s = 0.f; int c = 0;
    for (int e = 0; e < cnt; e++) {
        int m = map[col[e]];
        if (m >= 0) { s += d_p[m]; c++; }
    }
    d_score[i] = s / (float)(c < 1 ? 1 : c) + d_q[i] + pb[0];
}

// ---------------- per-graph top-k (bitonic 512) ----------------
__global__ void __launch_bounds__(512) topk_k(int npg, int k, int* __restrict__ perm_out) {
    __shared__ float sc[512];
    __shared__ int   id[512];
    int b = blockIdx.x, tid = threadIdx.x;
    if (tid < npg) {
        sc[tid] = d_score[b * npg + tid];
        id[tid] = b * npg + tid;
    } else {
        sc[tid] = -INFINITY;
        id[tid] = 0x7FFFFFFF;
    }
    __syncthreads();
    for (int kk = 2; kk <= 512; kk <<= 1) {
        for (int j = kk >> 1; j > 0; j >>= 1) {
            int i = tid, ixj = i ^ j;
            if (ixj > i) {
                float s1 = sc[i], s2 = sc[ixj];
                int i1 = id[i], i2 = id[ixj];
                bool beforeIxj = (s2 > s1) || (s2 == s1 && i2 < i1);
                bool up = ((i & kk) == 0);
                if (up ? beforeIxj : !beforeIxj) {
                    sc[i] = s2; sc[ixj] = s1;
                    id[i] = i2; id[ixj] = i1;
                }
            }
            __syncthreads();
        }
    }
    if (tid < k) {
        perm_out[b * k + tid] = id[tid];
        d_tsc[b * k + tid] = tanhf(sc[tid]);
    }
}

__global__ void compose_k() {
    int i = blockIdx.x * blockDim.x + threadIdx.x;
    if (i >= NAL2) return;
    int i1 = d_perm2s[i];
    int o = d_perm1[i1];
    d_permO2[i] = o;
    d_map2[o] = i;
}

__global__ void compact_k(int srcsel, int dstsel, const int* __restrict__ perm,
                          int n, int* __restrict__ map_or_null) {
    int g = blockIdx.x * blockDim.x + threadIdx.x;
    int w = g >> 5, lane = g & 31;
    if (w >= n) return;
    int src_row = perm[w];
    if (map_or_null && lane == 0) map_or_null[src_row] = w;
    float t = d_tsc[w];
    const float* S = selX(nullptr, srcsel);
    float* D = selXw(dstsel);
    float4 v = ((const float4*)(S + (size_t)src_row * HDIM))[lane];
    v.x *= t; v.y *= t; v.z *= t; v.w *= t;
    ((float4*)(D + (size_t)w * HDIM))[lane] = v;
}

// ---------------- MLP head ----------------
__global__ void head_k(const float* __restrict__ l1w, const float* __restrict__ l1b,
                       const float* __restrict__ l2w, const float* __restrict__ l2b,
                       float* __restrict__ out) {
    int b = blockIdx.x, h = threadIdx.x;
    float acc = l1b[h];
#pragma unroll 2
    for (int l = 0; l < NLAY; l++) {
        const float* xr = &d_xs[(l * BGRAPH + b) * HDIM];
#pragma unroll 8
        for (int kk = 0; kk < HDIM; kk++) {
            acc += xr[kk] * l1w[(l * HDIM + kk) * HDIM + h];
        }
    }
    acc = fmaxf(acc, 0.f);
    __shared__ float s0[128], s1[128];
    s0[h] = acc * l2w[h * 2 + 0];
    s1[h] = acc * l2w[h * 2 + 1];
    __syncthreads();
    for (int off = 64; off; off >>= 1) {
        if (h < off) { s0[h] += s0[h + off]; s1[h] += s1[h + off]; }
        __syncthreads();
    }
    if (h == 0) {
        float l0 = s0[0] + l2b[0];
        float l1 = s1[0] + l2b[1];
        float m = fmaxf(l0, l1);
        float lse = m + logf(expf(l0 - m) + expf(l1 - m));
        out[b * 2 + 0] = l0 - lse;
        out[b * 2 + 1] = l1 - lse;
    }
}

// ---------------- launch (gmean forked to a second stream) ----------------
static cudaStream_t g_s2;
static cudaEvent_t  g_evF[5], g_evJ[5];
static int g_streams_ready = 0;

extern "C" void kernel_launch(void* const* d_in, const int* in_sizes, int n_in,
                              void* d_out, int out_size) {
    const float* x    = (const float*)d_in[0];
    const int*   ei   = (const int*)d_in[1];
    const float* c1wr = (const float*)d_in[3];
    const float* c1ws = (const float*)d_in[4];
    const float* c1b  = (const float*)d_in[5];
    const float* cwr  = (const float*)d_in[6];
    const float* cws  = (const float*)d_in[7];
    const float* cb   = (const float*)d_in[8];
    const float* pwr  = (const float*)d_in[9];
    const float* pws  = (const float*)d_in[10];
    const float* pb   = (const float*)d_in[11];
    const float* l1w  = (const float*)d_in[12];
    const float* l1b  = (const float*)d_in[13];
    const float* l2w  = (const float*)d_in[14];
    const float* l2b  = (const float*)d_in[15];
    float* out = (float*)d_out;

    const int WPB = 256;

    if (!g_streams_ready) {   // first call is the uncaptured correctness run
        cudaStreamCreateWithFlags(&g_s2, cudaStreamNonBlocking);
        for (int i = 0; i < 5; i++) {
            cudaEventCreateWithFlags(&g_evF[i], cudaEventDisableTiming);
            cudaEventCreateWithFlags(&g_evJ[i], cudaEventDisableTiming);
        }
        g_streams_ready = 1;
    }

    int *perm1, *perm2s, *permO2, *map1, *map2;
    cudaGetSymbolAddress((void**)&perm1, d_perm1);
    cudaGetSymbolAddress((void**)&perm2s, d_perm2s);
    cudaGetSymbolAddress((void**)&permO2, d_permO2);
    cudaGetSymbolAddress((void**)&map1, d_map1);
    cudaGetSymbolAddress((void**)&map2, d_map2);

    // bucket build
    init_k<<<NNODE / WPB, WPB>>>();
    scatter_k<<<NEDGE / WPB, WPB>>>(ei);

    // conv1: x -> XA
    agg_full_g<<<NSM, 1024>>>(x, 0);
    gemm_k<<<NNODE / 64, 128>>>(x, 0, 1, c1wr, c1ws, c1b);
    cudaEventRecord(g_evF[0], 0);
    cudaStreamWaitEvent(g_s2, g_evF[0], 0);
    gmean_k<<<BGRAPH, 512, 0, g_s2>>>(x, 1, 0, NPG0, 1.0f / 400.0f);   // reads XA
    cudaEventRecord(g_evJ[0], g_s2);

    // conv2: XA -> XB
    agg_full_g<<<NSM, 1024>>>(x, 1);
    gemm_k<<<NNODE / 64, 128>>>(x, 1, 2, cwr + 0 * HDIM * HDIM, cws + 0 * HDIM * HDIM, cb + 0 * HDIM);
    cudaEventRecord(g_evF[1], 0);
    cudaStreamWaitEvent(g_s2, g_evF[1], 0);
    gmean_k<<<BGRAPH, 512, 0, g_s2>>>(x, 2, 1, NPG0, 1.0f / 400.0f);   // reads XB
    cudaEventRecord(g_evJ[1], g_s2);

    // pool1: XB -> space1 (compact XB -> XA); XA overwritten -> join gmean0 first
    dots_k<<<NNODE / 8, WPB>>>(x, 2, NNODE, pwr + 0 * HDIM, pws + 0 * HDIM);
    score1_k<<<NNODE / WPB, WPB>>>(pb + 0);
    topk_k<<<BGRAPH, 512>>>(NPG0, NPG1, perm1);
    cudaStreamWaitEvent(0, g_evJ[0], 0);
    compact_k<<<NAL1 / 8, WPB>>>(2, 1, perm1, NAL1, map1);

    // conv3 (space1): XA -> XB; XB overwritten -> join gmean1 first
    agg_c_g<<<NSM, 1024>>>(1, NPG1, perm1, map1);
    cudaStreamWaitEvent(0, g_evJ[1], 0);
    gemm_k<<<NAL1 / 64, 128>>>(x, 1, 2, cwr + 1 * HDIM * HDIM, cws + 1 * HDIM * HDIM, cb + 1 * HDIM);
    cudaEventRecord(g_evF[2], 0);
    cudaStreamWaitEvent(g_s2, g_evF[2], 0);
    gmean_k<<<BGRAPH, 512, 0, g_s2>>>(x, 2, 2, NPG1, 1.0f / 320.0f);   // reads XB
    cudaEventRecord(g_evJ[2], g_s2);

    // conv4 (space1): XB -> XA
    agg_c_g<<<NSM, 1024>>>(2, NPG1, perm1, map1);
    gemm_k<<<NAL1 / 64, 128>>>(x, 2, 1, cwr + 2 * HDIM * HDIM, cws + 2 * HDIM * HDIM, cb + 2 * HDIM);
    cudaEventRecord(g_evF[3], 0);
    cudaStreamWaitEvent(g_s2, g_evF[3], 0);
    gmean_k<<<BGRAPH, 512, 0, g_s2>>>(x, 1, 3, NPG1, 1.0f / 320.0f);   // reads XA
    cudaEventRecord(g_evJ[3], g_s2);

    // pool2: XA -> space2 (compact XA -> XB); XB overwritten -> join gmean2 first
    dots_k<<<NAL1 / 8, WPB>>>(x, 1, NAL1, pwr + 1 * HDIM, pws + 1 * HDIM);
    score2_k<<<NAL1 / WPB, WPB>>>(pb + 1, perm1, map1, NAL1);
    topk_k<<<BGRAPH, 512>>>(NPG1, NPG2, perm2s);
    compose_k<<<NAL2 / WPB, WPB>>>();
    cudaStreamWaitEvent(0, g_evJ[2], 0);
    compact_k<<<NAL2 / 8, WPB>>>(1, 2, perm2s, NAL2, nullptr);

    // conv5 (space2): XB -> XA; XA overwritten -> join gmean3 first
    agg_c_g<<<NSM, 1024>>>(2, NPG2, permO2, map2);
    cudaStreamWaitEvent(0, g_evJ[3], 0);
    gemm_k<<<NAL2 / 64, 128>>>(x, 2, 1, cwr + 3 * HDIM * HDIM, cws + 3 * HDIM * HDIM, cb + 3 * HDIM);
    cudaEventRecord(g_evF[4], 0);
    cudaStreamWaitEvent(g_s2, g_evF[4], 0);
    gmean_k<<<BGRAPH, 512, 0, g_s2>>>(x, 1, 4, NPG2, 1.0f / 256.0f);   // reads XA
    cudaEventRecord(g_evJ[4], g_s2);

    // head: needs all gmeans
    cudaStreamWaitEvent(0, g_evJ[4], 0);
    head_k<<<BGRAPH, HDIM>>>(l1w, l1b, l2w, l2b, out);
}